// round 2
// baseline (speedup 1.0000x reference)
#include <cuda_runtime.h>
#include <stdint.h>

#define ROW_N    2048
#define K_SEL    1024
#define NTHREADS 256
#define EPT      8          // elements per thread

__device__ __forceinline__ uint32_t f2u_ord(uint32_t b) {
    // order-preserving: ascending float -> ascending uint
    uint32_t mask = (uint32_t)(((int32_t)b) >> 31) | 0x80000000u;
    return b ^ mask;
}
__device__ __forceinline__ float u2f_ord(uint32_t u) {
    uint32_t mask = (uint32_t)(((int32_t)(~u)) >> 31) | 0x80000000u;
    return __uint_as_float(u ^ mask);
}

__global__ __launch_bounds__(NTHREADS, 8) void kta_kernel(const float* __restrict__ in,
                                                          float* __restrict__ out) {
    __shared__ uint32_t s_hist[256];
    __shared__ uint32_t s_woff[8];
    __shared__ uint32_t s_sel[2];

    const int t    = threadIdx.x;
    const int lane = t & 31;
    const int wid  = t >> 5;
    const size_t row_base = (size_t)blockIdx.x * ROW_N;

    const float4* in4  = (const float4*)(in  + row_base);
    float4*       out4 = (float4*)(out + row_base);

    // ---- load + transform into registers: 2 x float4 per thread ----
    uint32_t u[EPT];
#pragma unroll
    for (int v = 0; v < 2; v++) {
        float4 f = in4[t + v * NTHREADS];
        u[v*4+0] = f2u_ord(__float_as_uint(f.x));
        u[v*4+1] = f2u_ord(__float_as_uint(f.y));
        u[v*4+2] = f2u_ord(__float_as_uint(f.z));
        u[v*4+3] = f2u_ord(__float_as_uint(f.w));
    }

    // ---- 4-pass radix select (k-th smallest), match_any-aggregated histogram ----
    uint32_t prefix = 0;
    uint32_t krem   = K_SEL;

#pragma unroll
    for (int pass = 0; pass < 4; pass++) {
        const int shift = 24 - 8 * pass;
        const uint32_t hi_mask = (pass == 0) ? 0u : (0xFFFFFFFFu << (shift + 8));

        s_hist[t] = 0;
        __syncthreads();

#pragma unroll
        for (int e = 0; e < EPT; e++) {
            // sentinel digit 256 for non-matching elements
            uint32_t digit = ((u[e] & hi_mask) == prefix) ? ((u[e] >> shift) & 255u) : 256u;
            // aggregate equal digits within the warp: one atomic per group
            uint32_t peers  = __match_any_sync(0xFFFFFFFFu, digit);
            uint32_t leader = __ffs(peers) - 1u;
            if (lane == leader && digit < 256u)
                atomicAdd(&s_hist[digit], __popc(peers));
        }
        __syncthreads();

        // inclusive scan over 256 bins
        uint32_t cnt = s_hist[t];
        uint32_t inc = cnt;
#pragma unroll
        for (int o = 1; o < 32; o <<= 1) {
            uint32_t v = __shfl_up_sync(0xFFFFFFFFu, inc, o);
            if (lane >= o) inc += v;
        }
        if (lane == 31) s_woff[wid] = inc;
        __syncthreads();
        if (t == 0) {
            uint32_t run = 0;
#pragma unroll
            for (int w = 0; w < 8; w++) { uint32_t x = s_woff[w]; s_woff[w] = run; run += x; }
        }
        __syncthreads();
        inc += s_woff[wid];
        uint32_t exc = inc - cnt;

        if (exc < krem && krem <= inc) {   // exactly one thread true
            s_sel[0] = (uint32_t)t;
            s_sel[1] = exc;
        }
        __syncthreads();

        prefix |= s_sel[0] << shift;
        krem   -= s_sel[1];
    }

    const uint32_t T = prefix;  // transformed k-th smallest

    // ---- output from registers: zero everything <= T ----
#pragma unroll
    for (int v = 0; v < 2; v++) {
        float4 o;
        o.x = (u[v*4+0] <= T) ? 0.0f : u2f_ord(u[v*4+0]);
        o.y = (u[v*4+1] <= T) ? 0.0f : u2f_ord(u[v*4+1]);
        o.z = (u[v*4+2] <= T) ? 0.0f : u2f_ord(u[v*4+2]);
        o.w = (u[v*4+3] <= T) ? 0.0f : u2f_ord(u[v*4+3]);
        out4[t + v * NTHREADS] = o;
    }
}

extern "C" void kernel_launch(void* const* d_in, const int* in_sizes, int n_in,
                              void* d_out, int out_size) {
    const float* in = (const float*)d_in[0];
    float* out = (float*)d_out;
    int rows = in_sizes[0] / ROW_N;
    kta_kernel<<<rows, NTHREADS>>>(in, out);
}

// round 3
// speedup vs baseline: 1.2586x; 1.2586x over previous
#include <cuda_runtime.h>
#include <stdint.h>

#define ROW_N 2048
#define K_SEL 1024u
#define NT    256
#define NBIN  4096

__device__ __forceinline__ uint32_t f2u_ord(uint32_t b) {
    uint32_t m = (uint32_t)(((int32_t)b) >> 31) | 0x80000000u;
    return b ^ m;
}
__device__ __forceinline__ float u2f_ord(uint32_t u) {
    uint32_t m = (uint32_t)(((int32_t)(~u)) >> 31) | 0x80000000u;
    return __uint_as_float(u ^ m);
}

__global__ __launch_bounds__(NT, 8) void kta_kernel(const float* __restrict__ in,
                                                    float* __restrict__ out) {
    __shared__ uint32_t s_hist[NBIN];     // 16 KB
    __shared__ uint32_t s_cand[ROW_N];    // 8 KB (worst-case capacity)
    __shared__ uint32_t s_woff[8];
    __shared__ uint32_t s_sel[2];         // {bin, exclusive count}
    __shared__ uint32_t s_cnt;
    __shared__ uint32_t s_T;

    const int t    = threadIdx.x;
    const int lane = t & 31;
    const int wid  = t >> 5;
    const size_t base = (size_t)blockIdx.x * ROW_N;
    const float4* in4  = (const float4*)(in  + base);
    float4*       out4 = (float4*)(out + base);

    // ---- zero histogram (vectorized) + counters ----
    uint4* h4 = (uint4*)s_hist;
    const uint4 z = make_uint4(0, 0, 0, 0);
#pragma unroll
    for (int v = 0; v < NBIN / 4 / NT; v++) h4[t + v * NT] = z;
    if (t == 0) s_cnt = 0;

    // ---- load + transform into registers ----
    uint32_t u[8];
#pragma unroll
    for (int v = 0; v < 2; v++) {
        float4 f = in4[t + v * NT];
        u[v*4+0] = f2u_ord(__float_as_uint(f.x));
        u[v*4+1] = f2u_ord(__float_as_uint(f.y));
        u[v*4+2] = f2u_ord(__float_as_uint(f.z));
        u[v*4+3] = f2u_ord(__float_as_uint(f.w));
    }
    __syncthreads();

    // ---- single 12-bit histogram pass ----
#pragma unroll
    for (int e = 0; e < 8; e++) atomicAdd(&s_hist[u[e] >> 20], 1u);
    __syncthreads();

    // ---- sum 16 bins per thread, block scan, locate crossing bin ----
    uint32_t loc = 0;
#pragma unroll
    for (int v = 0; v < 4; v++) {
        uint4 b = h4[t * 4 + v];
        loc += b.x + b.y + b.z + b.w;
    }
    uint32_t inc = loc;
#pragma unroll
    for (int o = 1; o < 32; o <<= 1) {
        uint32_t vv = __shfl_up_sync(0xFFFFFFFFu, inc, o);
        if (lane >= o) inc += vv;
    }
    if (lane == 31) s_woff[wid] = inc;
    __syncthreads();
    if (t == 0) {
        uint32_t run = 0;
#pragma unroll
        for (int w = 0; w < 8; w++) { uint32_t x = s_woff[w]; s_woff[w] = run; run += x; }
    }
    __syncthreads();
    inc += s_woff[wid];
    uint32_t exc = inc - loc;

    if (exc < K_SEL && K_SEL <= inc) {   // exactly one thread
        uint32_t run = exc;
        uint32_t found = 0;
        for (int j = 0; j < 16; j++) {
            uint32_t c = s_hist[t * 16 + j];
            if (!found && run < K_SEL && K_SEL <= run + c) {
                s_sel[0] = (uint32_t)(t * 16 + j);
                s_sel[1] = run;
                found = 1;
            }
            run += c;
        }
    }
    __syncthreads();
    const uint32_t bin12 = s_sel[0];
    const uint32_t k2    = K_SEL - s_sel[1];   // rank within candidates, 1-based

    // ---- compact candidates (ballot-aggregated) ----
#pragma unroll
    for (int e = 0; e < 8; e++) {
        bool pred = (u[e] >> 20) == bin12;
        uint32_t m = __ballot_sync(0xFFFFFFFFu, pred);
        if (m) {
            uint32_t nb = __popc(m);
            uint32_t ldr = __ffs(m) - 1u;
            uint32_t bpos = 0;
            if (lane == ldr) bpos = atomicAdd(&s_cnt, nb);
            bpos = __shfl_sync(0xFFFFFFFFu, bpos, ldr);
            if (pred) s_cand[bpos + __popc(m & ((1u << lane) - 1u))] = u[e];
        }
    }
    __syncthreads();
    const uint32_t C = s_cnt;

    // ---- exact rank selection among C candidates (C ~ 30-80 typical) ----
    for (uint32_t i = t; i < C; i += NT) {
        uint32_t v = s_cand[i];
        uint32_t less = 0, leq = 0;
        for (uint32_t j = 0; j < C; j++) {
            uint32_t c = s_cand[j];          // broadcast LDS
            less += (c < v);
            leq  += (c <= v);
        }
        if (less < k2 && k2 <= leq) s_T = v; // k2-th smallest (dup-safe)
    }
    __syncthreads();
    const uint32_t T = s_T;

    // ---- output from registers: zero everything <= T ----
#pragma unroll
    for (int v = 0; v < 2; v++) {
        float4 o;
        o.x = (u[v*4+0] <= T) ? 0.0f : u2f_ord(u[v*4+0]);
        o.y = (u[v*4+1] <= T) ? 0.0f : u2f_ord(u[v*4+1]);
        o.z = (u[v*4+2] <= T) ? 0.0f : u2f_ord(u[v*4+2]);
        o.w = (u[v*4+3] <= T) ? 0.0f : u2f_ord(u[v*4+3]);
        out4[t + v * NT] = o;
    }
}

extern "C" void kernel_launch(void* const* d_in, const int* in_sizes, int n_in,
                              void* d_out, int out_size) {
    const float* in = (const float*)d_in[0];
    float* out = (float*)d_out;
    int rows = in_sizes[0] / ROW_N;
    kta_kernel<<<rows, NT>>>(in, out);
}